// round 1
// baseline (speedup 1.0000x reference)
#include <cuda_runtime.h>
#include <cstdint>
#include <cstddef>

// CTC batch cost (keras ctc_batch_cost semantics), prob-domain forward with
// per-8-step rescaling. B=256, T=512, C=256 (blank=255), U=64, S=129.
static constexpr int Bn   = 256;
static constexpr int Tn   = 512;
static constexpr int Cn   = 256;
static constexpr int Un   = 64;
static constexpr int BLANK = Cn - 1;
static constexpr float EPSF = 1e-7f;
static constexpr int DEPTH = 32;          // cp.async ring depth (32 KB smem)

__device__ __forceinline__ void cp16(uint32_t s, const float* g) {
    asm volatile("cp.async.ca.shared.global [%0], [%1], 16;\n" :: "r"(s), "l"(g));
}
__device__ __forceinline__ void cp_commit() {
    asm volatile("cp.async.commit_group;\n");
}
__device__ __forceinline__ void cp_wait_allbut() {
    asm volatile("cp.async.wait_group %0;\n" :: "n"(DEPTH - 1));
}

__global__ __launch_bounds__(32, 4)
void ctc_fwd_kernel(const int* __restrict__ y_true,
                    const float* __restrict__ y_pred,
                    float* __restrict__ out) {
    __shared__ float stg[DEPTH * Cn];     // 32 KB staging ring, one 1KB row/stage

    const int b    = blockIdx.x;
    const int lane = threadIdx.x;
    const float* g = y_pred + (size_t)b * Tn * Cn;
    const uint32_t sbase = (uint32_t)__cvta_generic_to_shared(stg);

    // ---- prologue: fill DEPTH stages (rows t=0..DEPTH-1), one group per row
    #pragma unroll 4
    for (int i = 0; i < DEPTH; i++) {
        uint32_t sa   = sbase + (uint32_t)(i * Cn + lane * 8) * 4u;
        const float* ga = g + i * Cn + lane * 8;
        cp16(sa, ga);
        cp16(sa + 16, ga + 4);
        cp_commit();
    }

    // ---- labels for my states: lane L owns states 4L..4L+3 (+ s=128 on lane 31)
    // odd states 4L+1, 4L+3 emit labels y[2L], y[2L+1]
    const int l0 = y_true[b * Un + 2 * lane];
    const int l1 = y_true[b * Un + 2 * lane + 1];
    const int lprev = __shfl_up_sync(0xffffffffu, l1, 1);        // y[2L-1]
    const float sk1 = (lane == 0) ? 0.f : ((l0 != lprev) ? 1.f : 0.f); // lane0: a[-1]=0 anyway
    const float sk3 = (l1 != l0) ? 1.f : 0.f;

    // ---- t = 0 init: alpha[0] = p(blank)+eps, alpha[1] = p(l0)+eps
    cp_wait_allbut();
    __syncwarp();
    float a0 = 0.f, a1 = 0.f, a2 = 0.f, a3 = 0.f, a4 = 0.f;
    {
        float pB = stg[BLANK];
        float p0 = stg[l0];
        if (lane == 0) { a0 = pB + EPSF; a1 = p0 + EPSF; }
    }
    __syncwarp();
    // refill slot 0 with row t=DEPTH
    {
        uint32_t sa   = sbase + (uint32_t)(lane * 8) * 4u;
        const float* ga = g + DEPTH * Cn + lane * 8;
        cp16(sa, ga);
        cp16(sa + 16, ga + 4);
        cp_commit();
    }

    float logZ = 0.f;
    const float Kc = 256.f;               // per-step compensation vs 1/C decay
    const float EK = 256.f * EPSF;

    // ---- main recursion, t = 1..T-1
    for (int t = 1; t < Tn; t++) {
        const int slot = t & (DEPTH - 1);
        cp_wait_allbut();
        __syncwarp();
        const float pB = stg[slot * Cn + BLANK];
        const float q0 = stg[slot * Cn + l0];
        const float q1 = stg[slot * Cn + l1];
        __syncwarp();                     // all lanes consumed slot before refill
        const int tn = t + DEPTH;
        if (tn < Tn) {
            uint32_t sa   = sbase + (uint32_t)(slot * Cn + lane * 8) * 4u;
            const float* ga = g + tn * Cn + lane * 8;
            cp16(sa, ga);
            cp16(sa + 16, ga + 4);
        }
        cp_commit();                      // empty group near the tail keeps wait math valid

        // v = 256*(p + eps)
        const float vB = fmaf(pB, Kc, EK);
        const float v0 = fmaf(q0, Kc, EK);
        const float v1 = fmaf(q1, Kc, EK);

        float pa3 = __shfl_up_sync(0xffffffffu, a3, 1);   // old alpha[4L-1]
        if (lane == 0) pa3 = 0.f;

        const float na0 = (a0 + pa3) * vB;                        // s=4L   (blank)
        const float na1 = fmaf(sk1, pa3, a0 + a1) * v0;           // s=4L+1 (label l0)
        const float na2 = (a1 + a2) * vB;                         // s=4L+2 (blank)
        const float na3 = fmaf(sk3, a1, a2 + a3) * v1;            // s=4L+3 (label l1)
        const float na4 = (lane == 31) ? (a3 + a4) * vB : 0.f;    // s=128  (blank)
        a0 = na0; a1 = na1; a2 = na2; a3 = na3; a4 = na4;

        if ((t & 7) == 7) {               // renormalize, bookkeep log scale
            float s = a0 + a1 + a2 + a3 + a4;
            #pragma unroll
            for (int o = 16; o; o >>= 1) s += __shfl_xor_sync(0xffffffffu, s, o);
            logZ += __logf(s);
            const float inv = 1.0f / s;
            a0 *= inv; a1 *= inv; a2 *= inv; a3 *= inv; a4 *= inv;
        }
    }

    // loss = -log(alpha[S-1] + alpha[S-2]); undo 511 applications of Kc
    if (lane == 31) {
        const float tail = a3 + a4;
        const float loss = -(__logf(tail) + logZ - 511.0f * __logf(256.0f));
        out[b] = loss;
    }
}

extern "C" void kernel_launch(void* const* d_in, const int* in_sizes, int n_in,
                              void* d_out, int out_size) {
    const int* y_true;
    const float* y_pred;
    if (in_sizes[0] == Bn * Un) {         // y_true first (metadata dict order)
        y_true = (const int*)d_in[0];
        y_pred = (const float*)d_in[1];
    } else {
        y_true = (const int*)d_in[1];
        y_pred = (const float*)d_in[0];
    }
    float* out = (float*)d_out;
    ctc_fwd_kernel<<<Bn, 32>>>(y_true, y_pred, out);
}

// round 2
// speedup vs baseline: 1.1303x; 1.1303x over previous
#include <cuda_runtime.h>
#include <cstdint>
#include <cstddef>

// CTC batch cost (keras ctc_batch_cost), prob-domain forward, power-of-2
// rescaling with deferred (pipelined) warp reduction.
// B=256, T=512, C=256 (blank=255), U=64, S=129. 1 warp per batch element.
static constexpr int Bn = 256, Tn = 512, Cn = 256, Un = 64;
static constexpr int BLANK = Cn - 1;
static constexpr float EPSF = 1e-7f;
static constexpr int DEPTH = 32;            // smem ring: 32 rows x 1KB

__device__ __forceinline__ void cp16(uint32_t s, const float* g) {
    asm volatile("cp.async.ca.shared.global [%0], [%1], 16;\n" :: "r"(s), "l"(g));
}
__device__ __forceinline__ void cp_commit() {
    asm volatile("cp.async.commit_group;\n");
}
template<int N>
__device__ __forceinline__ void cp_wait() {
    asm volatile("cp.async.wait_group %0;\n" :: "n"(N));
}

// One trellis step. Lane L owns states 4L..4L+3; a4 is state 128 on lane 31
// (junk-but-finite on other lanes; only enters the normalization sum, which is
// exactly bookkept, so harmless).
__device__ __forceinline__ void dp_step(float& a0, float& a1, float& a2,
                                        float& a3, float& a4,
                                        float vB, float v0, float v1,
                                        float sk1, float sk3, int lane) {
    float pa3 = __shfl_up_sync(0xffffffffu, a3, 1);
    if (lane == 0) pa3 = 0.f;
    float na0 = (a0 + pa3) * vB;
    float na1 = fmaf(sk1, pa3, a0 + a1) * v0;
    float na2 = (a1 + a2) * vB;
    float na3 = fmaf(sk3, a1, a2 + a3) * v1;
    float na4 = (a3 + a4) * vB;
    a0 = na0; a1 = na1; a2 = na2; a3 = na3; a4 = na4;
}

__global__ __launch_bounds__(32, 4)
void ctc_fwd_kernel(const int* __restrict__ y_true,
                    const float* __restrict__ y_pred,
                    float* __restrict__ out) {
    __shared__ float stg[DEPTH * Cn];
    const int b = blockIdx.x, lane = threadIdx.x;
    const float* g = y_pred + (size_t)b * Tn * Cn;
    const uint32_t sbase = (uint32_t)__cvta_generic_to_shared(stg);

    // ---- prologue: rows 0..31 in 8 commits of 4 rows each
    #pragma unroll
    for (int c = 0; c < 8; c++) {
        #pragma unroll
        for (int r = 0; r < 4; r++) {
            const int row = c * 4 + r;
            uint32_t sa = sbase + (uint32_t)(row * Cn + lane * 8) * 4u;
            const float* ga = g + row * Cn + lane * 8;
            cp16(sa, ga); cp16(sa + 16, ga + 4);
        }
        cp_commit();
    }

    const int l0 = y_true[b * Un + 2 * lane];
    const int l1 = y_true[b * Un + 2 * lane + 1];
    const int lprev = __shfl_up_sync(0xffffffffu, l1, 1);
    const float sk1 = (lane == 0) ? 0.f : ((l0 != lprev) ? 1.f : 0.f);
    const float sk3 = (l1 != l0) ? 1.f : 0.f;

    const float Kc = 256.f, EK = 256.f * EPSF;

    // ---- init (t=0) + peel t=1..3 (rows 0..3: first prologue commit)
    cp_wait<7>();
    __syncwarp();
    float a0 = 0.f, a1 = 0.f, a2 = 0.f, a3 = 0.f, a4 = 0.f;
    if (lane == 0) { a0 = stg[BLANK] + EPSF; a1 = stg[l0] + EPSF; }
    #pragma unroll
    for (int t = 1; t < 4; t++) {
        const float vB = fmaf(stg[t * Cn + BLANK], Kc, EK);
        const float v0 = fmaf(stg[t * Cn + l0], Kc, EK);
        const float v1 = fmaf(stg[t * Cn + l1], Kc, EK);
        dp_step(a0, a1, a2, a3, a4, vB, v0, v1, sk1, sk3, lane);
    }

    int   E  = 0;       // exact accumulated power-of-2 exponent
    float bf = 1.f;     // pipelined warp-sum (applied one pair later)

    // ---- main: 63 pairs of 4-step groups (t = 4..507), then final group 508..511
    // Group starting at row R: wait_group(6) guarantees rows R..R+3 resident
    // (commits = 8 + groups_done; needed = (R+3)/4 + 1; difference == 6 always).
    #pragma unroll 1
    for (int pp = 0; pp < 63; pp++) {
        const int R = 8 * pp + 4;

        // ===== group A: rows R..R+3 =====
        cp_wait<6>();
        __syncwarp();
        float vB[4], v0[4], v1[4];
        {
            const int sl = R & 31;
            #pragma unroll
            for (int i = 0; i < 4; i++) {
                const float* row = &stg[(sl + i) * Cn];
                vB[i] = fmaf(row[BLANK], Kc, EK);
                v0[i] = fmaf(row[l0],   Kc, EK);
                v1[i] = fmaf(row[l1],   Kc, EK);
            }
            #pragma unroll
            for (int i = 0; i < 4; i++) {           // refill rows R+28..R+31
                const int row = R + 28 + i;
                if (row < Tn) {
                    uint32_t sa = sbase + (uint32_t)(((row & 31) * Cn) + lane * 8) * 4u;
                    const float* ga = g + row * Cn + lane * 8;
                    cp16(sa, ga); cp16(sa + 16, ga + 4);
                }
            }
            cp_commit();
        }
        if (pp > 0) {  // apply previous pair's scale (exact 2^-e), lag ~5 steps
            const uint32_t bb = __float_as_uint(bf);
            const int ei = (int)(bb >> 23) - 127;
            const float r = __uint_as_float((uint32_t)(127 - ei) << 23);
            E += ei;
            a0 *= r; a1 *= r; a2 *= r; a3 *= r; a4 *= r;
        }
        dp_step(a0, a1, a2, a3, a4, vB[0], v0[0], v1[0], sk1, sk3, lane);
        dp_step(a0, a1, a2, a3, a4, vB[1], v0[1], v1[1], sk1, sk3, lane);
        dp_step(a0, a1, a2, a3, a4, vB[2], v0[2], v1[2], sk1, sk3, lane);
        dp_step(a0, a1, a2, a3, a4, vB[3], v0[3], v1[3], sk1, sk3, lane);

        // snapshot sum at t = 8pp+7; butterfly interleaved with group B steps
        float ls = ((a0 + a1) + (a2 + a3)) + a4;
        ls += __shfl_xor_sync(0xffffffffu, ls, 16);

        // ===== group B: rows R+4..R+7 =====
        cp_wait<6>();
        __syncwarp();
        {
            const int sl = (R + 4) & 31;
            #pragma unroll
            for (int i = 0; i < 4; i++) {
                const float* row = &stg[(sl + i) * Cn];
                vB[i] = fmaf(row[BLANK], Kc, EK);
                v0[i] = fmaf(row[l0],   Kc, EK);
                v1[i] = fmaf(row[l1],   Kc, EK);
            }
            #pragma unroll
            for (int i = 0; i < 4; i++) {           // refill rows R+32..R+35
                const int row = R + 32 + i;
                if (row < Tn) {
                    uint32_t sa = sbase + (uint32_t)(((row & 31) * Cn) + lane * 8) * 4u;
                    const float* ga = g + row * Cn + lane * 8;
                    cp16(sa, ga); cp16(sa + 16, ga + 4);
                }
            }
            cp_commit();
        }
        dp_step(a0, a1, a2, a3, a4, vB[0], v0[0], v1[0], sk1, sk3, lane);
        ls += __shfl_xor_sync(0xffffffffu, ls, 8);
        dp_step(a0, a1, a2, a3, a4, vB[1], v0[1], v1[1], sk1, sk3, lane);
        ls += __shfl_xor_sync(0xffffffffu, ls, 4);
        dp_step(a0, a1, a2, a3, a4, vB[2], v0[2], v1[2], sk1, sk3, lane);
        ls += __shfl_xor_sync(0xffffffffu, ls, 2);
        dp_step(a0, a1, a2, a3, a4, vB[3], v0[3], v1[3], sk1, sk3, lane);
        ls += __shfl_xor_sync(0xffffffffu, ls, 1);
        bf = ls;
    }

    // ===== final group: rows 508..511 =====
    cp_wait<6>();
    __syncwarp();
    {
        float vB[4], v0[4], v1[4];
        const int sl = 508 & 31;   // 28
        #pragma unroll
        for (int i = 0; i < 4; i++) {
            const float* row = &stg[(sl + i) * Cn];
            vB[i] = fmaf(row[BLANK], Kc, EK);
            v0[i] = fmaf(row[l0],   Kc, EK);
            v1[i] = fmaf(row[l1],   Kc, EK);
        }
        {   // apply last pair's scale
            const uint32_t bb = __float_as_uint(bf);
            const int ei = (int)(bb >> 23) - 127;
            const float r = __uint_as_float((uint32_t)(127 - ei) << 23);
            E += ei;
            a0 *= r; a1 *= r; a2 *= r; a3 *= r; a4 *= r;
        }
        dp_step(a0, a1, a2, a3, a4, vB[0], v0[0], v1[0], sk1, sk3, lane);
        dp_step(a0, a1, a2, a3, a4, vB[1], v0[1], v1[1], sk1, sk3, lane);
        dp_step(a0, a1, a2, a3, a4, vB[2], v0[2], v1[2], sk1, sk3, lane);
        dp_step(a0, a1, a2, a3, a4, vB[3], v0[3], v1[3], sk1, sk3, lane);
    }

    // loss = -log(actual tail); stored = actual * 256^511 * 2^-E
    if (lane == 31) {
        const float tail = a3 + a4;
        const float LN2 = 0.69314718055994530942f;
        out[b] = -(logf(tail) + (float)(E - 4088) * LN2);   // 4088 = 511*8
    }
}

extern "C" void kernel_launch(void* const* d_in, const int* in_sizes, int n_in,
                              void* d_out, int out_size) {
    const int* y_true;
    const float* y_pred;
    if (in_sizes[0] == Bn * Un) {
        y_true = (const int*)d_in[0];
        y_pred = (const float*)d_in[1];
    } else {
        y_true = (const int*)d_in[1];
        y_pred = (const float*)d_in[0];
    }
    ctc_fwd_kernel<<<Bn, 32>>>(y_true, y_pred, (float*)d_out);
}

// round 4
// speedup vs baseline: 1.4719x; 1.3023x over previous
#include <cuda_runtime.h>
#include <cstdint>
#include <cstddef>

// CTC batch cost (keras ctc_batch_cost), prob-domain forward, exact biased
// power-of-2 rescaling, cp.async.bulk streaming (64KB ring, 4 x 16KB quarters).
// B=256, T=512, C=256 (blank=255), U=64, S=129. One warp per batch element.
static constexpr int Bn = 256, Tn = 512, Cn = 256, Un = 64;
static constexpr int BLANK = Cn - 1;
static constexpr float EPSF = 1e-7f;
static constexpr float Kc = 256.f;      // exact power of 2
static constexpr int   BIAS = 48;       // working level ~2^(48+lag_growth)

__device__ __forceinline__ void mwait(uint32_t mbar, uint32_t parity) {
    asm volatile(
        "{\n\t.reg .pred P;\n"
        "WL_%=:\n\t"
        "mbarrier.try_wait.parity.acquire.cta.shared::cta.b64 P, [%0], %1, 0x989680;\n\t"
        "@P bra WD_%=;\n\t"
        "bra WL_%=;\n"
        "WD_%=:\n\t}"
        :: "r"(mbar), "r"(parity) : "memory");
}

// lane 0 (predicated): expect_tx + 16KB bulk copy gmem->smem, one mbarrier
__device__ __forceinline__ void bulk_fill(uint32_t mbar, uint32_t sdst,
                                          const float* gsrc, int lane) {
    asm volatile(
        "{\n\t.reg .pred P;\n\t"
        "setp.eq.s32 P, %3, 0;\n\t"
        "@P mbarrier.arrive.expect_tx.shared.b64 _, [%0], 16384;\n\t"
        "@P cp.async.bulk.shared::cta.global.mbarrier::complete_tx::bytes [%1], [%2], 16384, [%0];\n\t"
        "}"
        :: "r"(mbar), "r"(sdst), "l"(gsrc), "r"(lane) : "memory");
}

// Lane L owns states 4L..4L+3; a4 = state 128 on lane 31 only (0 elsewhere).
__device__ __forceinline__ void dp_step(float& a0, float& a1, float& a2,
                                        float& a3, float& a4,
                                        float vB, float v0, float v1,
                                        float sk1, float sk3, int lane) {
    float pa3 = __shfl_up_sync(0xffffffffu, a3, 1);
    if (lane == 0) pa3 = 0.f;
    float na0 = (a0 + pa3) * vB;
    float na1 = fmaf(sk1, pa3, a0 + a1) * v0;
    float na2 = (a1 + a2) * vB;
    float na3 = fmaf(sk3, a1, a2 + a3) * v1;
    float na4 = (lane == 31) ? (a3 + a4) * vB : 0.f;
    a0 = na0; a1 = na1; a2 = na2; a3 = na3; a4 = na4;
}

// v = 256 * fl(p + eps): the *256 is exact, so per-step factors match the
// reference's log-argument bit-for-bit.
#define LOADV(SLOT)                                                          \
    { _Pragma("unroll") for (int i_ = 0; i_ < 4; i_++) {                     \
        vB[i_] = (pB[((SLOT) + i_) * Cn] + EPSF) * Kc;                       \
        v0[i_] = (p0[((SLOT) + i_) * Cn] + EPSF) * Kc;                       \
        v1[i_] = (p1[((SLOT) + i_) * Cn] + EPSF) * Kc; } }

// exact biased rescale: multiply all states by 2^-sh, E += sh
#define APPLY()                                                              \
    { uint32_t bb_ = __float_as_uint(bf);                                    \
      int sh_ = (int)(bb_ >> 23) - 127 - BIAS;                               \
      if (sh_ < -120) sh_ = -120;                                            \
      E += sh_;                                                              \
      float r_ = __uint_as_float((uint32_t)(127 - sh_) << 23);               \
      a0 *= r_; a1 *= r_; a2 *= r_; a3 *= r_; a4 *= r_; }

#define DPS(i_) dp_step(a0,a1,a2,a3,a4, vB[i_],v0[i_],v1[i_], sk1,sk3, lane)

// A-group: apply pending scale, 4 steps, snapshot sum, start butterfly
#define GRPA(SLOT)                                                           \
    { float vB[4], v0[4], v1[4]; LOADV(SLOT); APPLY();                       \
      DPS(0); DPS(1); DPS(2); DPS(3);                                        \
      ls = ((a0 + a1) + (a2 + a3)) + a4;                                     \
      ls += __shfl_xor_sync(0xffffffffu, ls, 16); }

// B-group: 4 steps with butterfly stages interleaved; bf ready at end
#define GRPB(SLOT)                                                           \
    { float vB[4], v0[4], v1[4]; LOADV(SLOT);                                \
      DPS(0); ls += __shfl_xor_sync(0xffffffffu, ls, 8);                     \
      DPS(1); ls += __shfl_xor_sync(0xffffffffu, ls, 4);                     \
      DPS(2); ls += __shfl_xor_sync(0xffffffffu, ls, 2);                     \
      DPS(3); ls += __shfl_xor_sync(0xffffffffu, ls, 1);                     \
      bf = ls; }

// one quarter (16 rows = 16 steps): wait, optional refill, B A B A
#define QBLK(WQ, PAR, RQ, DOFILL, S)                                         \
    { mwait(mbase + 8u * (WQ), (PAR)); __syncwarp();                         \
      if (DOFILL) { bulk_fill(mbase + 8u * (RQ), sbase + (RQ) * 16384u, gR, lane); \
                    gR += 4096; }                                            \
      GRPB(S); GRPA((S) + 4); GRPB((S) + 8); GRPA((S) + 12); }

__global__ void ctc_fwd_kernel(const int* __restrict__ y_true,
                               const float* __restrict__ y_pred,
                               float* __restrict__ out) {
    extern __shared__ float stg[];                   // 64 rows x 256 f32 = 64KB
    __shared__ __align__(8) unsigned long long mb[4];
    const int b = blockIdx.x, lane = threadIdx.x;
    const float* g = y_pred + (size_t)b * Tn * Cn;
    const uint32_t sbase = (uint32_t)__cvta_generic_to_shared(stg);
    const uint32_t mbase = (uint32_t)__cvta_generic_to_shared(mb);

    if (lane == 0) {
#pragma unroll
        for (int q = 0; q < 4; q++)
            asm volatile("mbarrier.init.shared.b64 [%0], 1;" :: "r"(mbase + 8u * q) : "memory");
        asm volatile("fence.proxy.async.shared::cta;" ::: "memory");
    }
    __syncwarp();
#pragma unroll
    for (int q = 0; q < 4; q++)                      // prologue: rows 0..63
        bulk_fill(mbase + 8u * q, sbase + q * 16384u, g + q * 4096, lane);

    const int l0 = y_true[b * Un + 2 * lane];
    const int l1 = y_true[b * Un + 2 * lane + 1];
    const int lp = __shfl_up_sync(0xffffffffu, l1, 1);
    const float sk1 = (lane == 0) ? 0.f : ((l0 != lp) ? 1.f : 0.f);
    const float sk3 = (l1 != l0) ? 1.f : 0.f;

    const float* pB = stg + BLANK;
    const float* p0 = stg + l0;
    const float* p1 = stg + l1;

    // ---- peel: t=0 init + t=1..3 (rows 0-3, quarter 0, completion #1 -> par 0)
    mwait(mbase, 0u);
    __syncwarp();
    float a0 = 0.f, a1 = 0.f, a2 = 0.f, a3 = 0.f, a4 = 0.f;
    if (lane == 0) { a0 = pB[0] + EPSF; a1 = p0[0] + EPSF; }
#pragma unroll
    for (int t = 1; t < 4; t++) {
        float vB = (pB[t * Cn] + EPSF) * Kc;
        float v0 = (p0[t * Cn] + EPSF) * Kc;
        float v1 = (p1[t * Cn] + EPSF) * Kc;
        dp_step(a0, a1, a2, a3, a4, vB, v0, v1, sk1, sk3, lane);
    }

    float ls = 0.f, bf = 1.f;
    int   E  = 0;
    const float* gR = g + 64 * Cn;                   // next rows to stream: 64..

    // rows 4-15 (rest of quarter 0): A B A  (first A applies bf=1 -> pure bias)
    GRPA(4); GRPB(8); GRPA(12);

    // main: 7 x 4 quarters (rows 16..463), refills stream rows 64..511
#pragma unroll 1
    for (int i = 0; i < 7; i++) {
        const uint32_t pe = (uint32_t)(i & 1), po = pe ^ 1u;
        QBLK(1, pe, 0, true, 16);
        QBLK(2, pe, 1, true, 32);
        QBLK(3, pe, 2, true, 48);
        QBLK(0, po, 3, true, 0);
    }
    // remainder quarters: rows 464..511, all parity 1, no refill
    QBLK(1, 1u, 0, false, 16);
    QBLK(2, 1u, 0, false, 32);
    QBLK(3, 1u, 0, false, 48);

    // stored tail = true_tail * 256^511 * 2^-E  (E exactly bookkept)
    if (lane == 31) {
        const float LN2 = 0.69314718055994530942f;
        out[b] = -(logf(a3 + a4) + (float)(E - 4088) * LN2);
    }
}

extern "C" void kernel_launch(void* const* d_in, const int* in_sizes, int n_in,
                              void* d_out, int out_size) {
    const int* y_true;
    const float* y_pred;
    if (in_sizes[0] == Bn * Un) {
        y_true = (const int*)d_in[0];
        y_pred = (const float*)d_in[1];
    } else {
        y_true = (const int*)d_in[1];
        y_pred = (const float*)d_in[0];
    }
    cudaFuncSetAttribute(ctc_fwd_kernel,
                         cudaFuncAttributeMaxDynamicSharedMemorySize, 65536);
    ctc_fwd_kernel<<<Bn, 32, 65536>>>(y_true, y_pred, (float*)d_out);
}